// round 5
// baseline (speedup 1.0000x reference)
#include <cuda_runtime.h>

// Problem constants
#define NVAR 14
#define CCAT 2
#define EDIM 32
#define VNUM 3
#define DDIM 16
#define KSZ  3
#define KSTATES 16384      // 2^14
#define BBATCH 32

#define H1CH 32            // conv1 out channels (2*D)
#define H1SP 9             // 3x3
#define H1N  (H1CH*H1SP)   // 288
#define H2CH 16            // conv2 out channels (D)
#define H2SP 25            // 5x5
#define H2N  (H2CH*H2SP)   // 400
#define W2N  (H2CH*KSZ*KSZ) // 144 entries per input channel
#define MN   49            // 7x7

#define WARPS 8
#define BLOCKS_PER_V 128
#define STATES_PER_WARP (KSTATES/(BLOCKS_PER_V*WARPS))  // 16

// Precomputed scratch (no allocations allowed)
__device__ float g_B1[VNUM*NVAR*CCAT*H1N];
__device__ float g_C1[VNUM*H1N];

// ---------------------------------------------------------------------------
// Precompute B1[v,j,c,:] = (latent[j,c] @ lin_w[v, j*ED:(j+1)*ED, :]) @ W1[v]
// ---------------------------------------------------------------------------
__global__ void precompute_B1_kernel(const float* __restrict__ lat,
                                     const float* __restrict__ lin_w,
                                     const float* __restrict__ w1) {
    int b = blockIdx.x;            // v*NVAR*CCAT + j*CCAT + c
    int v = b / (NVAR*CCAT);
    int jc = b % (NVAR*CCAT);
    int j = jc / CCAT, c = jc % CCAT;
    __shared__ float A[4*DDIM];    // 64
    int t = threadIdx.x;
    if (t < 4*DDIM) {
        float a = 0.f;
        const float* L = lat + (j*CCAT + c)*EDIM;
        const float* W = lin_w + (size_t)v*(NVAR*EDIM*4*DDIM) + (size_t)(j*EDIM)*(4*DDIM) + t;
        #pragma unroll
        for (int e = 0; e < EDIM; e++) a += L[e] * W[e*(4*DDIM)];
        A[t] = a;
    }
    __syncthreads();
    if (t < H1N) {
        float s = 0.f;
        const float* W1 = w1 + (size_t)v*(4*DDIM*H1N) + t;
        #pragma unroll 8
        for (int i = 0; i < 4*DDIM; i++) s += A[i] * W1[i*H1N];
        g_B1[(size_t)b*H1N + t] = s;
    }
}

__global__ void precompute_C1_kernel(const float* __restrict__ lin_b,
                                     const float* __restrict__ w1,
                                     const float* __restrict__ b1) {
    int v = blockIdx.x;
    int t = threadIdx.x;           // 0..287
    float s = b1[v*H1CH + t/H1SP];
    const float* W1 = w1 + (size_t)v*(4*DDIM*H1N) + t;
    const float* lb = lin_b + v*(4*DDIM);
    #pragma unroll 8
    for (int i = 0; i < 4*DDIM; i++) s += lb[i] * W1[i*H1N];
    g_C1[v*H1N + t] = s;
}

// ---------------------------------------------------------------------------
// Main kernel: one warp per (state, v); per-v constants in shared memory.
// ---------------------------------------------------------------------------

// shared layout in floats
#define S_B1 0
#define S_C1 (S_B1 + NVAR*CCAT*H1N)     // +8064
#define S_W2 (S_C1 + H1N)               // +288
#define S_W3 (S_W2 + H1CH*W2N)          // +4608
#define S_B2 (S_W3 + H2CH*KSZ*KSZ)      // +144
#define S_B3 (S_B2 + 16)
#define S_X  (S_B3 + 16)
#define S_H2 (S_X + BBATCH*MN)          // +1568
#define S_M  (S_H2 + WARPS*H2N)         // +3200
#define SMEM_FLOATS (S_M + WARPS*64)    // +512  -> 18416 floats = 73664 B

__device__ __forceinline__ float elu_f(float x) {
    return x > 0.f ? x : (__expf(x) - 1.f);
}

__global__ void __launch_bounds__(WARPS*32)
emission_main_kernel(const float* __restrict__ x,
                     const float* __restrict__ w2,
                     const float* __restrict__ b2,
                     const float* __restrict__ w3,
                     const float* __restrict__ b3,
                     float* __restrict__ out) {
    extern __shared__ float smem[];
    const int tid  = threadIdx.x;
    const int lane = tid & 31;
    const int warp = tid >> 5;
    const int v    = blockIdx.x / BLOCKS_PER_V;
    const int blk  = blockIdx.x % BLOCKS_PER_V;

    // ---- stage in per-v constants ----
    for (int i = tid; i < NVAR*CCAT*H1N; i += blockDim.x)
        smem[S_B1 + i] = g_B1[(size_t)v*(NVAR*CCAT*H1N) + i];
    for (int i = tid; i < H1N; i += blockDim.x)
        smem[S_C1 + i] = g_C1[v*H1N + i];
    for (int i = tid; i < H1CH*W2N; i += blockDim.x)
        smem[S_W2 + i] = w2[(size_t)v*(H1CH*W2N) + i];
    for (int i = tid; i < H2CH*KSZ*KSZ; i += blockDim.x)
        smem[S_W3 + i] = w3[(size_t)v*(H2CH*KSZ*KSZ) + i];
    if (tid < H2CH) smem[S_B2 + tid] = b2[v*H2CH + tid];
    if (tid == 0)   smem[S_B3] = b3[v];
    for (int i = tid; i < BBATCH*MN; i += blockDim.x) {
        int bb = i / MN, p = i % MN;
        smem[S_X + i] = x[(size_t)bb*(VNUM*MN) + v*MN + p];
    }
    __syncthreads();

    float* __restrict__ sB1 = smem + S_B1;
    float* __restrict__ sC1 = smem + S_C1;
    float* __restrict__ sW2 = smem + S_W2;
    float* __restrict__ sW3 = smem + S_W3;
    float* __restrict__ sB2 = smem + S_B2;
    float* __restrict__ sX  = smem + S_X;
    float* __restrict__ h2w = smem + S_H2 + warp*H2N;
    float* __restrict__ mw  = smem + S_M  + warp*64;
    const float bias3 = smem[S_B3];

    const int s_base = (blk*WARPS + warp)*STATES_PER_WARP;

    for (int it = 0; it < STATES_PER_WARP; it++) {
        const int s = s_base + it;

        // ---- stage 1: h1pre = C1 + sum_j B1[j, bit_j(s)]; ELU ----
        // lane = conv1 output channel; each lane holds 9 spatial values
        float h1q[9];
        {
            const float* cp = sC1 + lane*H1SP;
            #pragma unroll
            for (int q = 0; q < 9; q++) h1q[q] = cp[q];
            #pragma unroll
            for (int j = 0; j < NVAR; j++) {
                int c = (s >> (NVAR-1-j)) & 1;
                const float* bp = sB1 + (j*CCAT + c)*H1N + lane*H1SP;
                #pragma unroll
                for (int q = 0; q < 9; q++) h1q[q] += bp[q];
            }
            #pragma unroll
            for (int q = 0; q < 9; q++) h1q[q] = elu_f(h1q[q]);
        }

        // ---- init h2 accumulator with bias ----
        for (int idx = lane; idx < H2N; idx += 32)
            h2w[idx] = sB2[idx / H2SP];
        __syncwarp();

        // ---- conv2 as 9 K=32 -> N=144 products, accumulated in registers ----
        float acc[5][9];
        #pragma unroll
        for (int k = 0; k < 5; k++)
            #pragma unroll
            for (int q = 0; q < 9; q++) acc[k][q] = 0.f;

        #pragma unroll 4
        for (int i = 0; i < H1CH; i++) {
            float hq[9];
            #pragma unroll
            for (int q = 0; q < 9; q++)
                hq[q] = __shfl_sync(0xffffffffu, h1q[q], i);
            const float* wrow = sW2 + i*W2N;
            float wr0 = wrow[lane];
            float wr1 = wrow[lane + 32];
            float wr2 = wrow[lane + 64];
            float wr3 = wrow[lane + 96];
            float wr4 = (lane < 16) ? wrow[lane + 128] : 0.f;
            #pragma unroll
            for (int q = 0; q < 9; q++) {
                acc[0][q] += wr0 * hq[q];
                acc[1][q] += wr1 * hq[q];
                acc[2][q] += wr2 * hq[q];
                acc[3][q] += wr3 * hq[q];
                acc[4][q] += wr4 * hq[q];
            }
        }

        // ---- scatter into h2 (distinct addresses within each q-group) ----
        #pragma unroll
        for (int q = 0; q < 9; q++) {
            const int u = q / 3, vx = q % 3;
            #pragma unroll
            for (int k = 0; k < 5; k++) {
                const int e = lane + 32*k;
                if (e < W2N) {
                    const int o = e / 9, t = e % 9;
                    const int ky = t / 3, kx = t % 3;
                    h2w[o*H2SP + (u+ky)*5 + (vx+kx)] += acc[k][q];
                }
            }
            __syncwarp();
        }

        // ---- ELU on h2 ----
        for (int idx = lane; idx < H2N; idx += 32)
            h2w[idx] = elu_f(h2w[idx]);
        __syncwarp();

        // ---- conv3 (gather form) -> m[49] ----
        for (int p = lane; p < MN; p += 32) {
            const int y = p / 7, xx = p % 7;
            float a = bias3;
            const int u0 = max(0, y-2), u1 = min(4, y);
            const int v0 = max(0, xx-2), v1 = min(4, xx);
            for (int u = u0; u <= u1; u++) {
                for (int vv = v0; vv <= v1; vv++) {
                    const float* hp = h2w + u*5 + vv;
                    const float* wp = sW3 + (y-u)*3 + (xx-vv);
                    #pragma unroll
                    for (int i = 0; i < H2CH; i++)
                        a += hp[i*H2SP] * wp[i*(KSZ*KSZ)];
                }
            }
            mw[p] = a;
        }
        __syncwarp();

        // ---- loss vs all 32 images: lane = batch index ----
        {
            float accb = 0.f;
            const float* xp = sX + lane*MN;
            #pragma unroll 7
            for (int p = 0; p < MN; p++) {
                float d = mw[p] - xp[p];
                accb += d * d;
            }
            out[(size_t)lane*(KSTATES*VNUM) + (size_t)s*VNUM + v] = -0.5f * accb;
        }
        __syncwarp();
    }
}

// ---------------------------------------------------------------------------
extern "C" void kernel_launch(void* const* d_in, const int* in_sizes, int n_in,
                              void* d_out, int out_size) {
    const float* x     = (const float*)d_in[0];
    const float* lat   = (const float*)d_in[1];
    const float* lin_w = (const float*)d_in[2];
    const float* lin_b = (const float*)d_in[3];
    const float* w1    = (const float*)d_in[4];
    const float* b1    = (const float*)d_in[5];
    const float* w2    = (const float*)d_in[6];
    const float* b2    = (const float*)d_in[7];
    const float* w3    = (const float*)d_in[8];
    const float* b3    = (const float*)d_in[9];
    float* out = (float*)d_out;

    (void)in_sizes; (void)n_in; (void)out_size;

    precompute_B1_kernel<<<VNUM*NVAR*CCAT, H1N>>>(lat, lin_w, w1);
    precompute_C1_kernel<<<VNUM, H1N>>>(lin_b, w1, b1);

    static_assert(SMEM_FLOATS*4 == 73664, "smem layout");
    cudaFuncSetAttribute(emission_main_kernel,
                         cudaFuncAttributeMaxDynamicSharedMemorySize,
                         SMEM_FLOATS * (int)sizeof(float));

    emission_main_kernel<<<VNUM*BLOCKS_PER_V, WARPS*32, SMEM_FLOATS*sizeof(float)>>>(
        x, w2, b2, w3, b3, out);
}

// round 7
// speedup vs baseline: 1.5709x; 1.5709x over previous
#include <cuda_runtime.h>

// Problem constants
#define NVAR 14
#define CCAT 2
#define EDIM 32
#define VNUM 3
#define DDIM 16
#define KSZ  3
#define KSTATES 16384      // 2^14
#define BBATCH 32

#define H1CH 32            // conv1 out channels (2*D)
#define H1SP 9             // 3x3
#define H1N  (H1CH*H1SP)   // 288
#define H2CH 16            // conv2 out channels (D)
#define H2SP 25            // 5x5
#define H2N  (H2CH*H2SP)   // 400
#define W2N  (H2CH*KSZ*KSZ) // 144 entries per input channel
#define MN   49            // 7x7

#define WARPS 8
#define BLOCKS_PER_V 148
#define TOTAL_WARPS_PER_V (BLOCKS_PER_V*WARPS)        // 1184
#define QSTATES (KSTATES / TOTAL_WARPS_PER_V)         // 13
#define RSTATES (KSTATES - QSTATES*TOTAL_WARPS_PER_V) // 992

// Precomputed scratch (no allocations allowed)
__device__ float g_B1[VNUM*NVAR*CCAT*H1N];
__device__ float g_C1[VNUM*H1N];
__device__ float g_D1[VNUM*NVAR*H1N];   // delta per bit position b (0..13)
__device__ float g_E1[VNUM*H1N];        // base = C1 + sum_j B1[j,0]

// ---------------------------------------------------------------------------
// Precompute B1[v,j,c,:] = (latent[j,c] @ lin_w[v, j*ED:(j+1)*ED, :]) @ W1[v]
// ---------------------------------------------------------------------------
__global__ void precompute_B1_kernel(const float* __restrict__ lat,
                                     const float* __restrict__ lin_w,
                                     const float* __restrict__ w1) {
    int b = blockIdx.x;            // v*NVAR*CCAT + j*CCAT + c
    int v = b / (NVAR*CCAT);
    int jc = b % (NVAR*CCAT);
    int j = jc / CCAT, c = jc % CCAT;
    __shared__ float A[4*DDIM];    // 64
    int t = threadIdx.x;
    if (t < 4*DDIM) {
        float a = 0.f;
        const float* L = lat + (j*CCAT + c)*EDIM;
        const float* W = lin_w + (size_t)v*(NVAR*EDIM*4*DDIM) + (size_t)(j*EDIM)*(4*DDIM) + t;
        #pragma unroll
        for (int e = 0; e < EDIM; e++) a += L[e] * W[e*(4*DDIM)];
        A[t] = a;
    }
    __syncthreads();
    if (t < H1N) {
        float s = 0.f;
        const float* W1 = w1 + (size_t)v*(4*DDIM*H1N) + t;
        #pragma unroll 8
        for (int i = 0; i < 4*DDIM; i++) s += A[i] * W1[i*H1N];
        g_B1[(size_t)b*H1N + t] = s;
    }
}

__global__ void precompute_C1_kernel(const float* __restrict__ lin_b,
                                     const float* __restrict__ w1,
                                     const float* __restrict__ b1) {
    int v = blockIdx.x;
    int t = threadIdx.x;           // 0..287
    float s = b1[v*H1CH + t/H1SP];
    const float* W1 = w1 + (size_t)v*(4*DDIM*H1N) + t;
    const float* lb = lin_b + v*(4*DDIM);
    #pragma unroll 8
    for (int i = 0; i < 4*DDIM; i++) s += lb[i] * W1[i*H1N];
    g_C1[v*H1N + t] = s;
}

// D1[v, b, :] = B1[v, j=13-b, 1, :] - B1[v, j=13-b, 0, :]
// E1[v, :]    = C1[v, :] + sum_j B1[v, j, 0, :]
__global__ void precompute_D1E1_kernel() {
    int v = blockIdx.x;
    int t = threadIdx.x;  // 0..287
    float e = g_C1[v*H1N + t];
    #pragma unroll
    for (int j = 0; j < NVAR; j++) {
        float b0 = g_B1[(size_t)((v*NVAR + j)*CCAT + 0)*H1N + t];
        float b1v = g_B1[(size_t)((v*NVAR + j)*CCAT + 1)*H1N + t];
        e += b0;
        int b = NVAR - 1 - j;    // bit position for variable j
        g_D1[(size_t)(v*NVAR + b)*H1N + t] = b1v - b0;
    }
    g_E1[v*H1N + t] = e;
}

// ---------------------------------------------------------------------------
// Main kernel: one warp per contiguous state range; per-v constants in shared.
// ---------------------------------------------------------------------------

// shared layout in floats
#define S_D1 0
#define S_E1 (S_D1 + NVAR*H1N)          // +4032
#define S_W2 (S_E1 + H1N)               // +288
#define S_W3 (S_W2 + H1CH*W2N)          // +4608
#define S_B2 (S_W3 + H2CH*KSZ*KSZ)      // +144
#define S_X  (S_B2 + 16)                // +16
#define S_H2 (S_X + BBATCH*MN)          // +1568
#define S_M  (S_H2 + WARPS*H2N)         // +3200
#define SMEM_FLOATS (S_M + WARPS*64)    // +512 -> 14368 floats = 57472 B

__device__ __forceinline__ float elu_f(float x) {
    return x > 0.f ? x : (__expf(x) - 1.f);
}

__global__ void __launch_bounds__(WARPS*32, 3)
emission_main_kernel(const float* __restrict__ x,
                     const float* __restrict__ w2,
                     const float* __restrict__ b2,
                     const float* __restrict__ w3,
                     const float* __restrict__ b3,
                     float* __restrict__ out) {
    extern __shared__ float smem[];
    const int tid  = threadIdx.x;
    const int lane = tid & 31;
    const int warp = tid >> 5;
    const int v    = blockIdx.x / BLOCKS_PER_V;
    const int blk  = blockIdx.x % BLOCKS_PER_V;

    // ---- stage in per-v constants ----
    for (int i = tid; i < NVAR*H1N; i += blockDim.x)
        smem[S_D1 + i] = g_D1[(size_t)v*(NVAR*H1N) + i];
    for (int i = tid; i < H1N; i += blockDim.x)
        smem[S_E1 + i] = g_E1[v*H1N + i];
    for (int i = tid; i < H1CH*W2N; i += blockDim.x)
        smem[S_W2 + i] = w2[(size_t)v*(H1CH*W2N) + i];
    for (int i = tid; i < H2CH*KSZ*KSZ; i += blockDim.x)
        smem[S_W3 + i] = w3[(size_t)v*(H2CH*KSZ*KSZ) + i];
    if (tid < H2CH) smem[S_B2 + tid] = b2[v*H2CH + tid];
    for (int i = tid; i < BBATCH*MN; i += blockDim.x) {
        int bb = i / MN, p = i % MN;
        smem[S_X + i] = x[(size_t)bb*(VNUM*MN) + v*MN + p];
    }
    __syncthreads();

    float* __restrict__ sD1 = smem + S_D1;
    float* __restrict__ sE1 = smem + S_E1;
    float* __restrict__ sW2 = smem + S_W2;
    float* __restrict__ sW3 = smem + S_W3;
    float* __restrict__ sB2 = smem + S_B2;
    float* __restrict__ sX  = smem + S_X;
    float* __restrict__ h2w = smem + S_H2 + warp*H2N;
    float* __restrict__ mw  = smem + S_M  + warp*64;
    const float bias3 = b3[v];

    // contiguous state range for this warp
    const int wid    = blk*WARPS + warp;
    const int nst    = QSTATES + (wid < RSTATES ? 1 : 0);
    const int start  = wid*QSTATES + (wid < RSTATES ? wid : RSTATES);

    // ---- build initial pre-ELU h1 in registers ----
    float h1pre[9];
    {
        const float* ep = sE1 + lane*H1SP;
        #pragma unroll
        for (int q = 0; q < 9; q++) h1pre[q] = ep[q];
        #pragma unroll
        for (int b = 0; b < NVAR; b++) {
            if ((start >> b) & 1) {
                const float* dp = sD1 + b*H1N + lane*H1SP;
                #pragma unroll
                for (int q = 0; q < 9; q++) h1pre[q] += dp[q];
            }
        }
    }

    for (int it = 0; it < nst; it++) {
        const int s = start + it;

        // ---- incremental update: flip the bits that changed (avg ~2) ----
        if (it) {
            unsigned diff = (unsigned)(s ^ (s - 1));
            do {
                int b = __ffs(diff) - 1;
                diff &= diff - 1;
                float sg = ((s >> b) & 1) ? 1.f : -1.f;
                const float* dp = sD1 + b*H1N + lane*H1SP;
                #pragma unroll
                for (int q = 0; q < 9; q++) h1pre[q] = fmaf(sg, dp[q], h1pre[q]);
            } while (diff);
        }

        float h1q[9];
        #pragma unroll
        for (int q = 0; q < 9; q++) h1q[q] = elu_f(h1pre[q]);

        // ---- zero h2 accumulator (bias folded into conv3's ELU load) ----
        for (int idx = lane; idx < H2N; idx += 32)
            h2w[idx] = 0.f;
        __syncwarp();

        // ---- conv2 as 9 K=32 -> N=144 products, accumulated in registers ----
        float acc[5][9];
        #pragma unroll
        for (int k = 0; k < 5; k++)
            #pragma unroll
            for (int q = 0; q < 9; q++) acc[k][q] = 0.f;

        #pragma unroll 4
        for (int i = 0; i < H1CH; i++) {
            float hq[9];
            #pragma unroll
            for (int q = 0; q < 9; q++)
                hq[q] = __shfl_sync(0xffffffffu, h1q[q], i);
            const float* wrow = sW2 + i*W2N;
            float wr0 = wrow[lane];
            float wr1 = wrow[lane + 32];
            float wr2 = wrow[lane + 64];
            float wr3 = wrow[lane + 96];
            float wr4 = (lane < 16) ? wrow[lane + 128] : 0.f;
            #pragma unroll
            for (int q = 0; q < 9; q++) {
                acc[0][q] += wr0 * hq[q];
                acc[1][q] += wr1 * hq[q];
                acc[2][q] += wr2 * hq[q];
                acc[3][q] += wr3 * hq[q];
                acc[4][q] += wr4 * hq[q];
            }
        }

        // ---- scatter into h2 (all 144 targets distinct within each q) ----
        #pragma unroll
        for (int q = 0; q < 9; q++) {
            const int u = q / 3, vx = q % 3;
            #pragma unroll
            for (int k = 0; k < 5; k++) {
                const int e = lane + 32*k;
                if (e < W2N) {
                    const int o = e / 9, t = e % 9;
                    const int ky = t / 3, kx = t % 3;
                    h2w[o*H2SP + (u+ky)*5 + (vx+kx)] += acc[k][q];
                }
            }
            __syncwarp();
        }

        // ---- init m with bias3 ----
        for (int idx = lane; idx < MN; idx += 32)
            mw[idx] = bias3;
        __syncwarp();

        // ---- conv3: lane = input position; bias+ELU fused; 9 register
        //      accumulators, then 9 conflict-free RMW scatter rounds ----
        if (lane < H2SP) {
            const int u  = lane / 5, vv = lane % 5;
            float val[9];
            #pragma unroll
            for (int t = 0; t < 9; t++) val[t] = 0.f;
            #pragma unroll
            for (int i = 0; i < H2CH; i++) {
                float h = elu_f(h2w[i*H2SP + lane] + sB2[i]);
                const float* wp = sW3 + i*(KSZ*KSZ);
                #pragma unroll
                for (int t = 0; t < 9; t++) val[t] += h * wp[t];
            }
            #pragma unroll
            for (int t = 0; t < 9; t++) {
                const int ky = t / 3, kx = t % 3;
                mw[(u+ky)*7 + (vv+kx)] += val[t];   // distinct addrs per round
                __syncwarp(0x01ffffffu);
            }
        }
        __syncwarp();

        // ---- loss vs all 32 images: lane = batch index ----
        {
            float accb = 0.f;
            const float* xp = sX + lane*MN;
            #pragma unroll 7
            for (int p = 0; p < MN; p++) {
                float d = mw[p] - xp[p];
                accb += d * d;
            }
            out[(size_t)lane*(KSTATES*VNUM) + (size_t)s*VNUM + v] = -0.5f * accb;
        }
        __syncwarp();
    }
}

// ---------------------------------------------------------------------------
extern "C" void kernel_launch(void* const* d_in, const int* in_sizes, int n_in,
                              void* d_out, int out_size) {
    const float* x     = (const float*)d_in[0];
    const float* lat   = (const float*)d_in[1];
    const float* lin_w = (const float*)d_in[2];
    const float* lin_b = (const float*)d_in[3];
    const float* w1    = (const float*)d_in[4];
    const float* b1    = (const float*)d_in[5];
    const float* w2    = (const float*)d_in[6];
    const float* b2    = (const float*)d_in[7];
    const float* w3    = (const float*)d_in[8];
    const float* b3    = (const float*)d_in[9];
    float* out = (float*)d_out;

    (void)in_sizes; (void)n_in; (void)out_size;

    precompute_B1_kernel<<<VNUM*NVAR*CCAT, H1N>>>(lat, lin_w, w1);
    precompute_C1_kernel<<<VNUM, H1N>>>(lin_b, w1, b1);
    precompute_D1E1_kernel<<<VNUM, H1N>>>();

    static_assert(SMEM_FLOATS*4 == 57472, "smem layout");
    cudaFuncSetAttribute(emission_main_kernel,
                         cudaFuncAttributeMaxDynamicSharedMemorySize,
                         SMEM_FLOATS * (int)sizeof(float));

    emission_main_kernel<<<VNUM*BLOCKS_PER_V, WARPS*32, SMEM_FLOATS*sizeof(float)>>>(
        x, w2, b2, w3, b3, out);
}

// round 9
// speedup vs baseline: 1.8479x; 1.1763x over previous
#include <cuda_runtime.h>

// Problem constants
#define NVAR 14
#define CCAT 2
#define EDIM 32
#define VNUM 3
#define DDIM 16
#define KSZ  3
#define KSTATES 16384      // 2^14
#define BBATCH 32

#define H1CH 32            // conv1 out channels (2*D)
#define H1SP 9             // 3x3
#define H1N  (H1CH*H1SP)   // 288
#define H2CH 16            // conv2 out channels (D)
#define H2SP 25            // 5x5
#define H2N  (H2CH*H2SP)   // 400
#define W2N  (H2CH*KSZ*KSZ) // 144 entries per input channel
#define MN   49            // 7x7

#define WARPS 8
#define BLOCKS_PER_V 148
#define TOTAL_WARPS_PER_V (BLOCKS_PER_V*WARPS)        // 1184
#define QSTATES (KSTATES / TOTAL_WARPS_PER_V)         // 13
#define RSTATES (KSTATES - QSTATES*TOTAL_WARPS_PER_V) // 992

// Precomputed scratch (no allocations allowed)
__device__ float g_B1[VNUM*NVAR*CCAT*H1N];
__device__ float g_C1[VNUM*H1N];
__device__ float g_D1[VNUM*NVAR*H1N];   // delta per bit position b (0..13)
__device__ float g_E1[VNUM*H1N];        // base = C1 + sum_j B1[j,0]

// ---------------------------------------------------------------------------
// Precompute B1[v,j,c,:] = (latent[j,c] @ lin_w[v, j*ED:(j+1)*ED, :]) @ W1[v]
// ---------------------------------------------------------------------------
__global__ void precompute_B1_kernel(const float* __restrict__ lat,
                                     const float* __restrict__ lin_w,
                                     const float* __restrict__ w1) {
    int b = blockIdx.x;            // v*NVAR*CCAT + j*CCAT + c
    int v = b / (NVAR*CCAT);
    int jc = b % (NVAR*CCAT);
    int j = jc / CCAT, c = jc % CCAT;
    __shared__ float A[4*DDIM];    // 64
    int t = threadIdx.x;
    if (t < 4*DDIM) {
        float a = 0.f;
        const float* L = lat + (j*CCAT + c)*EDIM;
        const float* W = lin_w + (size_t)v*(NVAR*EDIM*4*DDIM) + (size_t)(j*EDIM)*(4*DDIM) + t;
        #pragma unroll
        for (int e = 0; e < EDIM; e++) a += L[e] * W[e*(4*DDIM)];
        A[t] = a;
    }
    __syncthreads();
    if (t < H1N) {
        float s = 0.f;
        const float* W1 = w1 + (size_t)v*(4*DDIM*H1N) + t;
        #pragma unroll 8
        for (int i = 0; i < 4*DDIM; i++) s += A[i] * W1[i*H1N];
        g_B1[(size_t)b*H1N + t] = s;
    }
}

__global__ void precompute_C1_kernel(const float* __restrict__ lin_b,
                                     const float* __restrict__ w1,
                                     const float* __restrict__ b1) {
    int v = blockIdx.x;
    int t = threadIdx.x;           // 0..287
    float s = b1[v*H1CH + t/H1SP];
    const float* W1 = w1 + (size_t)v*(4*DDIM*H1N) + t;
    const float* lb = lin_b + v*(4*DDIM);
    #pragma unroll 8
    for (int i = 0; i < 4*DDIM; i++) s += lb[i] * W1[i*H1N];
    g_C1[v*H1N + t] = s;
}

// D1[v, b, :] = B1[v, j=13-b, 1, :] - B1[v, j=13-b, 0, :]
// E1[v, :]    = C1[v, :] + sum_j B1[v, j, 0, :]
__global__ void precompute_D1E1_kernel() {
    int v = blockIdx.x;
    int t = threadIdx.x;  // 0..287
    float e = g_C1[v*H1N + t];
    #pragma unroll
    for (int j = 0; j < NVAR; j++) {
        float b0 = g_B1[(size_t)((v*NVAR + j)*CCAT + 0)*H1N + t];
        float b1v = g_B1[(size_t)((v*NVAR + j)*CCAT + 1)*H1N + t];
        e += b0;
        int b = NVAR - 1 - j;    // bit position for variable j
        g_D1[(size_t)(v*NVAR + b)*H1N + t] = b1v - b0;
    }
    g_E1[v*H1N + t] = e;
}

// ---------------------------------------------------------------------------
// Main kernel: one warp per contiguous state range; per-v constants in shared.
// ---------------------------------------------------------------------------

// shared layout in floats (all vector-accessed region starts are multiples of
// 4 floats = 16 bytes; S_H1S/S_M are multiples of 16 floats)
#define S_D1  0
#define S_E1  (S_D1 + NVAR*H1N)           // +4032  -> 4032
#define S_W2  (S_E1 + H1N)                // +288   -> 4320
#define S_W3  (S_W2 + H1CH*W2N)           // +4608  -> 8928
#define S_B2  (S_W3 + H2CH*12)            // +192   -> 9120
#define S_X   (S_B2 + 16)                 // +16    -> 9136
#define S_H1S (S_X + BBATCH*MN)           // +1568  -> 10704 (16-float aligned)
#define S_H2  (S_H1S + WARPS*H1CH*12)     // +3072  -> 13776
#define S_M   (S_H2 + WARPS*H2N)          // +3200  -> 16976
#define SMEM_FLOATS (S_M + WARPS*64)      // +512   -> 17488 floats = 69952 B

__device__ __forceinline__ float elu_f(float x) {
    return x > 0.f ? x : (__expf(x) - 1.f);
}

__global__ void __launch_bounds__(WARPS*32, 3)
emission_main_kernel(const float* __restrict__ x,
                     const float* __restrict__ w2,
                     const float* __restrict__ b2,
                     const float* __restrict__ w3,
                     const float* __restrict__ b3,
                     float* __restrict__ out) {
    extern __shared__ float smem[];
    const int tid  = threadIdx.x;
    const int lane = tid & 31;
    const int warp = tid >> 5;
    const int v    = blockIdx.x / BLOCKS_PER_V;
    const int blk  = blockIdx.x % BLOCKS_PER_V;

    // ---- stage in per-v constants ----
    for (int i = tid; i < NVAR*H1N; i += blockDim.x)
        smem[S_D1 + i] = g_D1[(size_t)v*(NVAR*H1N) + i];
    for (int i = tid; i < H1N; i += blockDim.x)
        smem[S_E1 + i] = g_E1[v*H1N + i];
    for (int i = tid; i < H1CH*W2N; i += blockDim.x)
        smem[S_W2 + i] = w2[(size_t)v*(H1CH*W2N) + i];
    // w3 padded: 9 taps per channel stored in 12-float rows (rows 16B aligned)
    if (tid < H2CH*KSZ*KSZ) {
        int i = tid / 9, t = tid % 9;
        smem[S_W3 + i*12 + t] = w3[(size_t)v*(H2CH*KSZ*KSZ) + tid];
    }
    if (tid < H2CH) smem[S_B2 + tid] = b2[v*H2CH + tid];
    for (int i = tid; i < BBATCH*MN; i += blockDim.x) {
        int bb = i / MN, p = i % MN;
        smem[S_X + i] = x[(size_t)bb*(VNUM*MN) + v*MN + p];
    }
    __syncthreads();

    float* __restrict__ sD1 = smem + S_D1;
    float* __restrict__ sE1 = smem + S_E1;
    float* __restrict__ sW2 = smem + S_W2;
    float* __restrict__ sW3 = smem + S_W3;
    float* __restrict__ sB2 = smem + S_B2;
    float* __restrict__ sX  = smem + S_X;
    float* __restrict__ h1w = smem + S_H1S + warp*(H1CH*12);
    float* __restrict__ h2w = smem + S_H2 + warp*H2N;
    float* __restrict__ mw  = smem + S_M  + warp*64;
    const float bias3 = b3[v];

    // contiguous state range for this warp
    const int wid    = blk*WARPS + warp;
    const int nst    = QSTATES + (wid < RSTATES ? 1 : 0);
    const int start  = wid*QSTATES + (wid < RSTATES ? wid : RSTATES);

    // ---- build initial pre-ELU h1 in registers ----
    float h1pre[9];
    {
        const float* ep = sE1 + lane*H1SP;
        #pragma unroll
        for (int q = 0; q < 9; q++) h1pre[q] = ep[q];
        #pragma unroll
        for (int b = 0; b < NVAR; b++) {
            if ((start >> b) & 1) {
                const float* dp = sD1 + b*H1N + lane*H1SP;
                #pragma unroll
                for (int q = 0; q < 9; q++) h1pre[q] += dp[q];
            }
        }
    }

    for (int it = 0; it < nst; it++) {
        const int s = start + it;

        // ---- incremental update: flip the bits that changed (avg ~2) ----
        if (it) {
            unsigned diff = (unsigned)(s ^ (s - 1));
            do {
                int b = __ffs(diff) - 1;
                diff &= diff - 1;
                float sg = ((s >> b) & 1) ? 1.f : -1.f;
                const float* dp = sD1 + b*H1N + lane*H1SP;
                #pragma unroll
                for (int q = 0; q < 9; q++) h1pre[q] = fmaf(sg, dp[q], h1pre[q]);
            } while (diff);
        }

        // ---- ELU + publish h1 (lane = channel) to padded smem row ----
        {
            float4 p0, p1;
            p0.x = elu_f(h1pre[0]); p0.y = elu_f(h1pre[1]);
            p0.z = elu_f(h1pre[2]); p0.w = elu_f(h1pre[3]);
            p1.x = elu_f(h1pre[4]); p1.y = elu_f(h1pre[5]);
            p1.z = elu_f(h1pre[6]); p1.w = elu_f(h1pre[7]);
            float p8 = elu_f(h1pre[8]);
            float* row = h1w + lane*12;
            *(float4*)(row)     = p0;
            *(float4*)(row + 4) = p1;
            row[8] = p8;
        }

        // ---- zero h2 accumulator (bias folded into conv3's ELU load) ----
        for (int idx = lane; idx < H2N; idx += 32)
            h2w[idx] = 0.f;
        __syncwarp();

        // ---- conv2 as 9 K=32 -> N=144 products, accumulated in registers;
        //      h1 row broadcast via float4 loads (no shfl) ----
        float acc[5][9];
        #pragma unroll
        for (int k = 0; k < 5; k++)
            #pragma unroll
            for (int q = 0; q < 9; q++) acc[k][q] = 0.f;

        #pragma unroll 4
        for (int i = 0; i < H1CH; i++) {
            const float* hrow = h1w + i*12;
            float4 ha = *(const float4*)(hrow);
            float4 hb = *(const float4*)(hrow + 4);
            float  hc = hrow[8];
            const float* wrow = sW2 + i*W2N;
            float wr0 = wrow[lane];
            float wr1 = wrow[lane + 32];
            float wr2 = wrow[lane + 64];
            float wr3 = wrow[lane + 96];
            float wr4 = (lane < 16) ? wrow[lane + 128] : 0.f;
            #pragma unroll
            for (int k = 0; k < 5; k++) {
                float w = (k==0)?wr0:(k==1)?wr1:(k==2)?wr2:(k==3)?wr3:wr4;
                acc[k][0] += w * ha.x;
                acc[k][1] += w * ha.y;
                acc[k][2] += w * ha.z;
                acc[k][3] += w * ha.w;
                acc[k][4] += w * hb.x;
                acc[k][5] += w * hb.y;
                acc[k][6] += w * hb.z;
                acc[k][7] += w * hb.w;
                acc[k][8] += w * hc;
            }
        }

        // ---- scatter into h2 (all 144 targets distinct within each q) ----
        #pragma unroll
        for (int q = 0; q < 9; q++) {
            const int u = q / 3, vx = q % 3;
            #pragma unroll
            for (int k = 0; k < 5; k++) {
                const int e = lane + 32*k;
                if (e < W2N) {
                    const int o = e / 9, t = e % 9;
                    const int ky = t / 3, kx = t % 3;
                    h2w[o*H2SP + (u+ky)*5 + (vx+kx)] += acc[k][q];
                }
            }
            __syncwarp();
        }

        // ---- init m with bias3 ----
        for (int idx = lane; idx < MN; idx += 32)
            mw[idx] = bias3;
        __syncwarp();

        // ---- conv3: lane = input position; bias+ELU fused; broadcast
        //      float4 weight loads; 9 conflict-free RMW scatter rounds ----
        if (lane < H2SP) {
            const int u  = lane / 5, vv = lane % 5;
            float4 b2a = *(const float4*)(sB2);
            float4 b2b = *(const float4*)(sB2 + 4);
            float4 b2c = *(const float4*)(sB2 + 8);
            float4 b2d = *(const float4*)(sB2 + 12);
            float b2r[16] = {b2a.x,b2a.y,b2a.z,b2a.w, b2b.x,b2b.y,b2b.z,b2b.w,
                             b2c.x,b2c.y,b2c.z,b2c.w, b2d.x,b2d.y,b2d.z,b2d.w};
            float val[9];
            #pragma unroll
            for (int t = 0; t < 9; t++) val[t] = 0.f;
            #pragma unroll
            for (int i = 0; i < H2CH; i++) {
                float h = elu_f(h2w[i*H2SP + lane] + b2r[i]);
                const float* wrow = sW3 + i*12;
                float4 wA = *(const float4*)(wrow);
                float4 wB = *(const float4*)(wrow + 4);
                float  w8 = wrow[8];
                val[0] += h * wA.x;
                val[1] += h * wA.y;
                val[2] += h * wA.z;
                val[3] += h * wA.w;
                val[4] += h * wB.x;
                val[5] += h * wB.y;
                val[6] += h * wB.z;
                val[7] += h * wB.w;
                val[8] += h * w8;
            }
            #pragma unroll
            for (int t = 0; t < 9; t++) {
                const int ky = t / 3, kx = t % 3;
                mw[(u+ky)*7 + (vv+kx)] += val[t];   // distinct addrs per round
                __syncwarp(0x01ffffffu);
            }
        }
        __syncwarp();

        // ---- loss vs all 32 images: lane = batch index; m via broadcast
        //      float4 loads ----
        {
            float accb = 0.f;
            const float* xp = sX + lane*MN;
            #pragma unroll
            for (int j = 0; j < 12; j++) {
                float4 mv = *(const float4*)(mw + 4*j);
                float d0 = mv.x - xp[4*j + 0];
                float d1 = mv.y - xp[4*j + 1];
                float d2 = mv.z - xp[4*j + 2];
                float d3 = mv.w - xp[4*j + 3];
                accb += d0*d0 + d1*d1 + d2*d2 + d3*d3;
            }
            float d48 = mw[48] - xp[48];
            accb += d48*d48;
            out[(size_t)lane*(KSTATES*VNUM) + (size_t)s*VNUM + v] = -0.5f * accb;
        }
        __syncwarp();
    }
}

// ---------------------------------------------------------------------------
extern "C" void kernel_launch(void* const* d_in, const int* in_sizes, int n_in,
                              void* d_out, int out_size) {
    const float* x     = (const float*)d_in[0];
    const float* lat   = (const float*)d_in[1];
    const float* lin_w = (const float*)d_in[2];
    const float* lin_b = (const float*)d_in[3];
    const float* w1    = (const float*)d_in[4];
    const float* b1    = (const float*)d_in[5];
    const float* w2    = (const float*)d_in[6];
    const float* b2    = (const float*)d_in[7];
    const float* w3    = (const float*)d_in[8];
    const float* b3    = (const float*)d_in[9];
    float* out = (float*)d_out;

    (void)in_sizes; (void)n_in; (void)out_size;

    precompute_B1_kernel<<<VNUM*NVAR*CCAT, H1N>>>(lat, lin_w, w1);
    precompute_C1_kernel<<<VNUM, H1N>>>(lin_b, w1, b1);
    precompute_D1E1_kernel<<<VNUM, H1N>>>();

    cudaFuncSetAttribute(emission_main_kernel,
                         cudaFuncAttributeMaxDynamicSharedMemorySize,
                         SMEM_FLOATS * (int)sizeof(float));

    emission_main_kernel<<<VNUM*BLOCKS_PER_V, WARPS*32, SMEM_FLOATS*sizeof(float)>>>(
        x, w2, b2, w3, b3, out);
}